// round 15
// baseline (speedup 1.0000x reference)
#include <cuda_runtime.h>
#include <stdint.h>

// ============================================================================
// FourierEmbedding via warp-level bf16 mma.sync (m16n8k16), 3-term hi/lo split.
// R14: ONE CTA per SM (TM=128, 512 thr) + DOUBLE-BUFFERED full B images.
// Rationale: co-resident CTAs phase-lock (anti-phase is unstable), so the 2nd
// CTA never hides serial phases; 1 CTA frees smem for two 67.6KB B buffers so
// every weight image streams during the previous GEMM/featgen window.
// cp.async.wait_group 1 waits only the older group (in-flight stage keeps
// flying). GEMM1 always reads B0, GEMM2/3 read B1/B0 alternately:
//   images: w1[d]->B0, w2[d]->B1, (w3->B0).
// Warp grid 4(row)x4(col), warp tile 32x32, fully unrolled inner loop (R13).
// ============================================================================

static constexpr int NROWS   = 131072;
static constexpr int TM      = 128;
static constexpr int THREADS = 512;
static constexpr int RS      = 528;               // image row stride (bytes)
static constexpr int IMG     = 128 * RS;          // 67584 B per weight image
static constexpr int SA      = 0;                 // A image: 128 rows x RS
static constexpr int B0      = TM * RS;           // 67584
static constexpr int B1      = B0 + IMG;          // 135168
static constexpr int REDO    = B1 + IMG;          // 202752
static constexpr int SMEM_BYTES = REDO + 4 * 128 * 8;  // 206848 -> 1 CTA/SM

__device__ __align__(16) unsigned char g_wimg[9 * IMG];

// ---------------------------------------------------------------------------
static __device__ __forceinline__ uint32_t smem_u32(const void* p) {
    uint32_t a;
    asm("{ .reg .u64 t; cvta.to.shared.u64 t, %1; cvt.u32.u64 %0, t; }"
        : "=r"(a) : "l"(p));
    return a;
}
static __device__ __forceinline__ uint32_t cvt_bf16x2(float b, float a) {
    uint32_t r;
    asm("cvt.rn.bf16x2.f32 %0, %1, %2;" : "=r"(r) : "f"(b), "f"(a));
    return r;
}
static __device__ __forceinline__ void pack_hilo(float a, float b,
                                                 uint32_t& hi, uint32_t& lo) {
    hi = cvt_bf16x2(b, a);
    const float ra = a - __uint_as_float(hi << 16);
    const float rb = b - __uint_as_float(hi & 0xffff0000u);
    lo = cvt_bf16x2(rb, ra);
}
static __device__ __forceinline__ void cp_async16(uint32_t dst, const void* src) {
    asm volatile("cp.async.cg.shared.global [%0], [%1], 16;"
                 :: "r"(dst), "l"(src) : "memory");
}
#define CP_COMMIT() asm volatile("cp.async.commit_group;" ::: "memory")
#define CP_WAIT1()  asm volatile("cp.async.wait_group 1;" ::: "memory")
#define CP_WAIT0()  asm volatile("cp.async.wait_group 0;" ::: "memory")
#define BAR_GRP(id) asm volatile("bar.sync %0, 128;" :: "r"(id) : "memory")

static __device__ __forceinline__ void ldsm4(uint32_t (&r)[4], uint32_t addr) {
    asm volatile("ldmatrix.sync.aligned.m8n8.x4.shared.b16 {%0,%1,%2,%3}, [%4];"
        : "=r"(r[0]), "=r"(r[1]), "=r"(r[2]), "=r"(r[3]) : "r"(addr));
}
static __device__ __forceinline__ void mma16816(float* c, const uint32_t* a,
                                                uint32_t b0, uint32_t b1) {
    asm("mma.sync.aligned.m16n8k16.row.col.f32.bf16.bf16.f32 "
        "{%0,%1,%2,%3},{%4,%5,%6,%7},{%8,%9},{%0,%1,%2,%3};"
        : "+f"(c[0]), "+f"(c[1]), "+f"(c[2]), "+f"(c[3])
        : "r"(a[0]), "r"(a[1]), "r"(a[2]), "r"(a[3]), "r"(b0), "r"(b1));
}

// K=128, 3-term bf16 GEMM. Warp tile 32x32, fully unrolled (R13).
static __device__ __forceinline__ void gemm_bf16x3(uint32_t aB, uint32_t bB,
                                                   float (&acc)[2][4][4]) {
#pragma unroll
    for (int ks = 0; ks < 8; ++ks) {
        const uint32_t kb = (uint32_t)ks * 32u;
        uint32_t ah[2][4], al[2][4], bh[2][4], bl[2][4];
        ldsm4(ah[0], aB + kb);
        ldsm4(ah[1], aB + 16u * RS + kb);
        ldsm4(bh[0], bB + kb);
        ldsm4(bh[1], bB + 16u * RS + kb);
        ldsm4(al[0], aB + kb + 256u);
        ldsm4(al[1], aB + 16u * RS + kb + 256u);
#pragma unroll
        for (int mt = 0; mt < 2; ++mt)
#pragma unroll
            for (int p = 0; p < 2; ++p) {
                mma16816(acc[mt][2 * p],     ah[mt], bh[p][0], bh[p][1]);
                mma16816(acc[mt][2 * p + 1], ah[mt], bh[p][2], bh[p][3]);
            }
        ldsm4(bl[0], bB + kb + 256u);
        ldsm4(bl[1], bB + 16u * RS + kb + 256u);
#pragma unroll
        for (int mt = 0; mt < 2; ++mt)
#pragma unroll
            for (int p = 0; p < 2; ++p) {
                mma16816(acc[mt][2 * p],     al[mt], bh[p][0], bh[p][1]);
                mma16816(acc[mt][2 * p + 1], al[mt], bh[p][2], bh[p][3]);
            }
#pragma unroll
        for (int mt = 0; mt < 2; ++mt)
#pragma unroll
            for (int p = 0; p < 2; ++p) {
                mma16816(acc[mt][2 * p],     ah[mt], bl[p][0], bl[p][1]);
                mma16816(acc[mt][2 * p + 1], ah[mt], bl[p][2], bl[p][3]);
            }
    }
}

// ---------------------------------------------------------------------------
// pre-kernel: build 9 weight images (transposed [n][k], hi/lo bf16, stride RS)
// ---------------------------------------------------------------------------
__global__ void convert_weights_kernel(const float* __restrict__ w1,
                                       const float* __restrict__ w2,
                                       const float* __restrict__ w3) {
    const int t = blockIdx.x * blockDim.x + threadIdx.x;  // 9*128*64 = 73728
    const int img = t >> 13;
    const int rem = t & 8191;
    const int n = rem >> 6;
    const int p = rem & 63;          // k-pair
    const float* src;
    if (img < 4)      src = w1 + img * (129 * 128);
    else if (img < 8) src = w2 + (img - 4) * (128 * 128);
    else              src = w3;
    const float v0 = src[(2 * p) * 128 + n];
    const float v1 = src[(2 * p + 1) * 128 + n];
    uint32_t hi, lo;
    pack_hilo(v0, v1, hi, lo);
    unsigned char* dst = g_wimg + img * IMG + n * RS + p * 4;
    *reinterpret_cast<uint32_t*>(dst)       = hi;
    *reinterpret_cast<uint32_t*>(dst + 256) = lo;
}

// ---------------------------------------------------------------------------
__global__ __launch_bounds__(THREADS, 1)
void fe_mma_kernel(const float* __restrict__ cont,   // [N,4]
                   const float* __restrict__ freqs,  // [4,64]
                   const float* __restrict__ w1,     // [4,129,128]
                   const float* __restrict__ b1,     // [4,128]
                   const float* __restrict__ ln1g,   // [4,128]
                   const float* __restrict__ ln1b,   // [4,128]
                   const float* __restrict__ b2,     // [4,128]
                   const float* __restrict__ outg,   // [128]
                   const float* __restrict__ outb,   // [128]
                   const float* __restrict__ b3,     // [128]
                   float* __restrict__ out)          // [N,128]
{
    extern __shared__ unsigned char smem[];
    const uint32_t sbase = smem_u32(smem);
    float2* red = reinterpret_cast<float2*>(smem + REDO);  // [4 wx][128 rows]

    const int tid  = threadIdx.x;
    const int lane = tid & 31;
    const int wid  = tid >> 5;
    const int wy = wid & 3, wx = wid >> 2;    // 4 row groups x 4 col groups
    const int rg = wy * 32, nb = wx * 32;
    const int g = lane >> 2, m = lane & 3;
    const int row0 = blockIdx.x * TM;

    int rr[4];
#pragma unroll
    for (int j = 0; j < 4; ++j) rr[j] = rg + j * 8 + g;

    const uint32_t aBase = sbase + SA
        + (uint32_t)(rg + (lane & 7) + 8 * ((lane >> 3) & 1)) * RS
        + (uint32_t)(lane >> 4) * 16u;
    const uint32_t bRow = (uint32_t)(nb + (lane & 7) + 8 * (lane >> 4)) * RS
        + (uint32_t)((lane >> 3) & 1) * 16u;
    const uint32_t bB0 = sbase + B0 + bRow;
    const uint32_t bB1 = sbase + B1 + bRow;

    auto stage = [&](int img, int bufOff) {
        const unsigned char* src = g_wimg + (size_t)img * IMG;
        for (int i = tid; i < IMG / 16; i += THREADS)
            cp_async16(sbase + bufOff + (uint32_t)i * 16u, src + i * 16);
        CP_COMMIT();
    };

    float accE[2][4][4];
#pragma unroll
    for (int i = 0; i < 2; ++i)
#pragma unroll
        for (int j = 0; j < 4; ++j)
#pragma unroll
            for (int q = 0; q < 4; ++q) accE[i][j][q] = 0.0f;

    const int frow = tid >> 2;          // featgen: 4 threads per row (0..127)
    const int fb   = (tid & 3) * 16;    // 16 freqs each

    // prologue: w1[0] -> B0
    stage(0, B0);

#pragma unroll 1
    for (int d = 0; d < 4; ++d) {
        __syncthreads();   // S1: GEMM2(d-1) done reading B1 + s_A free

        stage(4 + d, B1);  // w2[d] -> B1 (flies under featgen + GEMM1)

        // featgen -> s_A (cos at k[0,64), sin at k[64,128), lo at +256 B)
        {
            const float x = cont[(row0 + frow) * 4 + d];
            uint32_t chi[8], clo[8], shi[8], slo[8];
#pragma unroll
            for (int p = 0; p < 8; ++p) {
                const float f0 = freqs[d * 64 + fb + 2 * p];
                const float f1 = freqs[d * 64 + fb + 2 * p + 1];
                float c0, s0, c1, s1;
                __sincosf(x * f0 * 6.283185307179586477f, &s0, &c0);
                __sincosf(x * f1 * 6.283185307179586477f, &s1, &c1);
                pack_hilo(c0, c1, chi[p], clo[p]);
                pack_hilo(s0, s1, shi[p], slo[p]);
            }
            unsigned char* rowp = smem + SA + frow * RS;
            *reinterpret_cast<uint4*>(rowp + fb * 2)            = make_uint4(chi[0], chi[1], chi[2], chi[3]);
            *reinterpret_cast<uint4*>(rowp + fb * 2 + 16)       = make_uint4(chi[4], chi[5], chi[6], chi[7]);
            *reinterpret_cast<uint4*>(rowp + 128 + fb * 2)      = make_uint4(shi[0], shi[1], shi[2], shi[3]);
            *reinterpret_cast<uint4*>(rowp + 128 + fb * 2 + 16) = make_uint4(shi[4], shi[5], shi[6], shi[7]);
            *reinterpret_cast<uint4*>(rowp + 256 + fb * 2)      = make_uint4(clo[0], clo[1], clo[2], clo[3]);
            *reinterpret_cast<uint4*>(rowp + 256 + fb * 2 + 16) = make_uint4(clo[4], clo[5], clo[6], clo[7]);
            *reinterpret_cast<uint4*>(rowp + 384 + fb * 2)      = make_uint4(slo[0], slo[1], slo[2], slo[3]);
            *reinterpret_cast<uint4*>(rowp + 384 + fb * 2 + 16) = make_uint4(slo[4], slo[5], slo[6], slo[7]);
        }
        CP_WAIT1();        // w1[d] -> B0 landed (w2[d] still flying)
        __syncthreads();   // S2

        // ---- GEMM1 (B0) ----
        float acc[2][4][4];
#pragma unroll
        for (int i = 0; i < 2; ++i)
#pragma unroll
            for (int j = 0; j < 4; ++j)
#pragma unroll
                for (int q = 0; q < 4; ++q) acc[i][j][q] = 0.0f;
        gemm_bf16x3(aBase, bB0, acc);
        __syncthreads();   // S3: GEMM1 reads of B0 + s_A done

        // stage next GEMM1 operand into B0 (flies under epi1 + GEMM2)
        stage(d < 3 ? d + 1 : 8, B0);   // w1[d+1] or w3

        // ---- epi1: + x*w1_last + b1, LN, ReLU -> s_A (bf16 hi/lo) ----
        {
            const float* w1l = w1 + d * (129 * 128) + 128 * 128;
            const float* b1d = b1 + d * 128;
            float2 wl[4], bb[4];
#pragma unroll
            for (int nt = 0; nt < 4; ++nt) {
                const int c = nb + 8 * nt + 2 * m;
                wl[nt] = *reinterpret_cast<const float2*>(w1l + c);
                bb[nt] = *reinterpret_cast<const float2*>(b1d + c);
            }
            float v[4][4][2];
            float sum[4], sq[4];
#pragma unroll
            for (int j = 0; j < 4; ++j) {
                const float xr = cont[(row0 + rr[j]) * 4 + d];
                float s = 0.f, q = 0.f;
#pragma unroll
                for (int nt = 0; nt < 4; ++nt) {
                    const float v0 = acc[j >> 1][nt][2 * (j & 1)]     + xr * wl[nt].x + bb[nt].x;
                    const float v1 = acc[j >> 1][nt][2 * (j & 1) + 1] + xr * wl[nt].y + bb[nt].y;
                    v[j][nt][0] = v0; v[j][nt][1] = v1;
                    s += v0 + v1; q += v0 * v0 + v1 * v1;
                }
                sum[j] = s; sq[j] = q;
            }
#pragma unroll
            for (int msk = 1; msk <= 2; msk <<= 1)
#pragma unroll
                for (int j = 0; j < 4; ++j) {
                    sum[j] += __shfl_xor_sync(0xffffffffu, sum[j], msk);
                    sq[j]  += __shfl_xor_sync(0xffffffffu, sq[j],  msk);
                }
            if (m == 0)
#pragma unroll
                for (int j = 0; j < 4; ++j)
                    red[wx * 128 + rr[j]] = make_float2(sum[j], sq[j]);
            BAR_GRP(wy + 1);
#pragma unroll
            for (int j = 0; j < 4; ++j)
#pragma unroll
                for (int ox = 0; ox < 4; ++ox)
                    if (ox != wx) {
                        const float2 o = red[ox * 128 + rr[j]];
                        sum[j] += o.x; sq[j] += o.y;
                    }
            const float* gd = ln1g + d * 128;
            const float* bd = ln1b + d * 128;
#pragma unroll
            for (int j = 0; j < 4; ++j) {
                const float mu = sum[j] * (1.0f / 128.0f);
                const float rs = rsqrtf(sq[j] * (1.0f / 128.0f) - mu * mu + 1e-5f);
                unsigned char* rowp = smem + SA + rr[j] * RS;
#pragma unroll
                for (int nt = 0; nt < 4; ++nt) {
                    const int c = nb + 8 * nt + 2 * m;
                    const float2 gg = *reinterpret_cast<const float2*>(gd + c);
                    const float2 ee = *reinterpret_cast<const float2*>(bd + c);
                    const float h0 = fmaxf((v[j][nt][0] - mu) * rs * gg.x + ee.x, 0.f);
                    const float h1 = fmaxf((v[j][nt][1] - mu) * rs * gg.y + ee.y, 0.f);
                    uint32_t hi, lo;
                    pack_hilo(h0, h1, hi, lo);
                    *reinterpret_cast<uint32_t*>(rowp + c * 2)       = hi;
                    *reinterpret_cast<uint32_t*>(rowp + 256 + c * 2) = lo;
                }
            }
        }
        CP_WAIT1();        // w2[d] -> B1 landed (next w1/w3 still flying)
        __syncthreads();   // S4

        // ---- GEMM2 (B1) -> accE ----
        gemm_bf16x3(aBase, bB1, accE);
    }

    __syncthreads();       // GEMM2(d=3) reads of s_A/B1 done

    // ---- epi2: + sum_d b2, LN(outg,outb), ReLU -> s_A ----
    {
        float v[4][4][2];
        float sum[4], sq[4];
        float2 bs[4];
#pragma unroll
        for (int nt = 0; nt < 4; ++nt) {
            const int c = nb + 8 * nt + 2 * m;
            bs[nt].x = b2[c] + b2[128 + c] + b2[256 + c] + b2[384 + c];
            bs[nt].y = b2[c + 1] + b2[128 + c + 1] + b2[256 + c + 1] + b2[384 + c + 1];
        }
#pragma unroll
        for (int j = 0; j < 4; ++j) {
            float s = 0.f, q = 0.f;
#pragma unroll
            for (int nt = 0; nt < 4; ++nt) {
                const float v0 = accE[j >> 1][nt][2 * (j & 1)]     + bs[nt].x;
                const float v1 = accE[j >> 1][nt][2 * (j & 1) + 1] + bs[nt].y;
                v[j][nt][0] = v0; v[j][nt][1] = v1;
                s += v0 + v1; q += v0 * v0 + v1 * v1;
            }
            sum[j] = s; sq[j] = q;
        }
#pragma unroll
        for (int msk = 1; msk <= 2; msk <<= 1)
#pragma unroll
            for (int j = 0; j < 4; ++j) {
                sum[j] += __shfl_xor_sync(0xffffffffu, sum[j], msk);
                sq[j]  += __shfl_xor_sync(0xffffffffu, sq[j],  msk);
            }
        if (m == 0)
#pragma unroll
            for (int j = 0; j < 4; ++j)
                red[wx * 128 + rr[j]] = make_float2(sum[j], sq[j]);
        BAR_GRP(wy + 1);
#pragma unroll
        for (int j = 0; j < 4; ++j)
#pragma unroll
            for (int ox = 0; ox < 4; ++ox)
                if (ox != wx) {
                    const float2 o = red[ox * 128 + rr[j]];
                    sum[j] += o.x; sq[j] += o.y;
                }
#pragma unroll
        for (int j = 0; j < 4; ++j) {
            const float mu = sum[j] * (1.0f / 128.0f);
            const float rs = rsqrtf(sq[j] * (1.0f / 128.0f) - mu * mu + 1e-5f);
            unsigned char* rowp = smem + SA + rr[j] * RS;
#pragma unroll
            for (int nt = 0; nt < 4; ++nt) {
                const int c = nb + 8 * nt + 2 * m;
                const float2 gg = *reinterpret_cast<const float2*>(outg + c);
                const float2 ee = *reinterpret_cast<const float2*>(outb + c);
                const float h0 = fmaxf((v[j][nt][0] - mu) * rs * gg.x + ee.x, 0.f);
                const float h1 = fmaxf((v[j][nt][1] - mu) * rs * gg.y + ee.y, 0.f);
                uint32_t hi, lo;
                pack_hilo(h0, h1, hi, lo);
                *reinterpret_cast<uint32_t*>(rowp + c * 2)       = hi;
                *reinterpret_cast<uint32_t*>(rowp + 256 + c * 2) = lo;
            }
        }
    }
    CP_WAIT0();            // w3 -> B0 landed
    __syncthreads();

    // ---- GEMM3 (B0) + b3 -> out ----
    float acc3[2][4][4];
#pragma unroll
    for (int i = 0; i < 2; ++i)
#pragma unroll
        for (int j = 0; j < 4; ++j)
#pragma unroll
            for (int q = 0; q < 4; ++q) acc3[i][j][q] = 0.0f;
    gemm_bf16x3(aBase, bB0, acc3);

#pragma unroll
    for (int j = 0; j < 4; ++j) {
        float* orow = out + (size_t)(row0 + rr[j]) * 128;
#pragma unroll
        for (int nt = 0; nt < 4; ++nt) {
            const int c = nb + 8 * nt + 2 * m;
            const float2 bb = *reinterpret_cast<const float2*>(b3 + c);
            *reinterpret_cast<float2*>(orow + c) =
                make_float2(acc3[j >> 1][nt][2 * (j & 1)]     + bb.x,
                            acc3[j >> 1][nt][2 * (j & 1) + 1] + bb.y);
        }
    }
}

// ---------------------------------------------------------------------------
extern "C" void kernel_launch(void* const* d_in, const int* in_sizes, int n_in,
                              void* d_out, int out_size)
{
    const float* cont  = (const float*)d_in[0];
    const float* freqs = (const float*)d_in[1];
    const float* w1    = (const float*)d_in[2];
    const float* b1    = (const float*)d_in[3];
    const float* ln1g  = (const float*)d_in[4];
    const float* ln1b  = (const float*)d_in[5];
    const float* w2    = (const float*)d_in[6];
    const float* b2    = (const float*)d_in[7];
    const float* outg  = (const float*)d_in[8];
    const float* outb  = (const float*)d_in[9];
    const float* w3    = (const float*)d_in[10];
    const float* b3    = (const float*)d_in[11];
    float* out = (float*)d_out;

    convert_weights_kernel<<<288, 256>>>(w1, w2, w3);

    cudaFuncSetAttribute(fe_mma_kernel,
                         cudaFuncAttributeMaxDynamicSharedMemorySize, SMEM_BYTES);
    fe_mma_kernel<<<NROWS / TM, THREADS, SMEM_BYTES>>>(
        cont, freqs, w1, b1, ln1g, ln1b, b2, outg, outb, b3, out);
}

// round 16
// speedup vs baseline: 1.0737x; 1.0737x over previous
#include <cuda_runtime.h>
#include <stdint.h>

// ============================================================================
// FourierEmbedding via warp-level bf16 mma.sync (m16n8k16), 3-term hi/lo split.
// R15 = R13 (best: 305.2us) + epilogue load hoisting: LN gamma/beta (and b3,
// cont) loads moved ABOVE the barrier asm whose "memory" clobber was pinning
// them after the sync -> removes ~300cyc exposed post-barrier LDG latency in
// every one of the 9 serial phases.
// CTA = 64 rows, 256 threads = 8 warps: wy(2 row groups) x wx(4 col groups),
// warp tile 32x32, fully unrolled ks loop. Weight images pre-built: [n][k]
// row-major, hi bf16 at k*2, lo at 256+k*2, row stride 528 B.
// ============================================================================

static constexpr int NROWS   = 131072;
static constexpr int TM      = 64;
static constexpr int THREADS = 256;
static constexpr int RS      = 528;               // image row stride (bytes)
static constexpr int IMG     = 128 * RS;          // 67584 B per weight image
static constexpr int SA      = 0;                 // A image: 64 rows
static constexpr int SB      = TM * RS;           // 33792
static constexpr int REDO    = SB + IMG;          // 101376
static constexpr int SMEM_BYTES = REDO + 4 * 64 * 8;  // 103424 -> 2 CTA/SM

__device__ __align__(16) unsigned char g_wimg[9 * IMG];

// ---------------------------------------------------------------------------
static __device__ __forceinline__ uint32_t smem_u32(const void* p) {
    uint32_t a;
    asm("{ .reg .u64 t; cvta.to.shared.u64 t, %1; cvt.u32.u64 %0, t; }"
        : "=r"(a) : "l"(p));
    return a;
}
static __device__ __forceinline__ uint32_t cvt_bf16x2(float b, float a) {
    uint32_t r;
    asm("cvt.rn.bf16x2.f32 %0, %1, %2;" : "=r"(r) : "f"(b), "f"(a));
    return r;
}
static __device__ __forceinline__ void pack_hilo(float a, float b,
                                                 uint32_t& hi, uint32_t& lo) {
    hi = cvt_bf16x2(b, a);
    const float ra = a - __uint_as_float(hi << 16);
    const float rb = b - __uint_as_float(hi & 0xffff0000u);
    lo = cvt_bf16x2(rb, ra);
}
static __device__ __forceinline__ void cp_async16(uint32_t dst, const void* src) {
    asm volatile("cp.async.cg.shared.global [%0], [%1], 16;"
                 :: "r"(dst), "l"(src) : "memory");
}
#define CP_COMMIT() asm volatile("cp.async.commit_group;" ::: "memory")
#define CP_WAIT0()  asm volatile("cp.async.wait_group 0;" ::: "memory")
#define BAR_GRP(id) asm volatile("bar.sync %0, 128;" :: "r"(id) : "memory")

static __device__ __forceinline__ void ldsm4(uint32_t (&r)[4], uint32_t addr) {
    asm volatile("ldmatrix.sync.aligned.m8n8.x4.shared.b16 {%0,%1,%2,%3}, [%4];"
        : "=r"(r[0]), "=r"(r[1]), "=r"(r[2]), "=r"(r[3]) : "r"(addr));
}
static __device__ __forceinline__ void mma16816(float* c, const uint32_t* a,
                                                uint32_t b0, uint32_t b1) {
    asm("mma.sync.aligned.m16n8k16.row.col.f32.bf16.bf16.f32 "
        "{%0,%1,%2,%3},{%4,%5,%6,%7},{%8,%9},{%0,%1,%2,%3};"
        : "+f"(c[0]), "+f"(c[1]), "+f"(c[2]), "+f"(c[3])
        : "r"(a[0]), "r"(a[1]), "r"(a[2]), "r"(a[3]), "r"(b0), "r"(b1));
}

// K=128, 3-term bf16 GEMM. Warp tile 32x32, fully unrolled (R13).
static __device__ __forceinline__ void gemm_bf16x3(uint32_t aB, uint32_t bB,
                                                   float (&acc)[2][4][4]) {
#pragma unroll
    for (int ks = 0; ks < 8; ++ks) {
        const uint32_t kb = (uint32_t)ks * 32u;
        uint32_t ah[2][4], al[2][4], bh[2][4], bl[2][4];
        ldsm4(ah[0], aB + kb);
        ldsm4(ah[1], aB + 16u * RS + kb);
        ldsm4(bh[0], bB + kb);
        ldsm4(bh[1], bB + 16u * RS + kb);
        ldsm4(al[0], aB + kb + 256u);
        ldsm4(al[1], aB + 16u * RS + kb + 256u);
#pragma unroll
        for (int mt = 0; mt < 2; ++mt)
#pragma unroll
            for (int p = 0; p < 2; ++p) {
                mma16816(acc[mt][2 * p],     ah[mt], bh[p][0], bh[p][1]);
                mma16816(acc[mt][2 * p + 1], ah[mt], bh[p][2], bh[p][3]);
            }
        ldsm4(bl[0], bB + kb + 256u);
        ldsm4(bl[1], bB + 16u * RS + kb + 256u);
#pragma unroll
        for (int mt = 0; mt < 2; ++mt)
#pragma unroll
            for (int p = 0; p < 2; ++p) {
                mma16816(acc[mt][2 * p],     al[mt], bh[p][0], bh[p][1]);
                mma16816(acc[mt][2 * p + 1], al[mt], bh[p][2], bh[p][3]);
            }
#pragma unroll
        for (int mt = 0; mt < 2; ++mt)
#pragma unroll
            for (int p = 0; p < 2; ++p) {
                mma16816(acc[mt][2 * p],     ah[mt], bl[p][0], bl[p][1]);
                mma16816(acc[mt][2 * p + 1], ah[mt], bl[p][2], bl[p][3]);
            }
    }
}

// ---------------------------------------------------------------------------
// pre-kernel: build 9 weight images (transposed [n][k], hi/lo bf16, stride RS)
// ---------------------------------------------------------------------------
__global__ void convert_weights_kernel(const float* __restrict__ w1,
                                       const float* __restrict__ w2,
                                       const float* __restrict__ w3) {
    const int t = blockIdx.x * blockDim.x + threadIdx.x;  // 9*128*64 = 73728
    const int img = t >> 13;
    const int rem = t & 8191;
    const int n = rem >> 6;
    const int p = rem & 63;          // k-pair
    const float* src;
    if (img < 4)      src = w1 + img * (129 * 128);
    else if (img < 8) src = w2 + (img - 4) * (128 * 128);
    else              src = w3;
    const float v0 = src[(2 * p) * 128 + n];
    const float v1 = src[(2 * p + 1) * 128 + n];
    uint32_t hi, lo;
    pack_hilo(v0, v1, hi, lo);
    unsigned char* dst = g_wimg + img * IMG + n * RS + p * 4;
    *reinterpret_cast<uint32_t*>(dst)       = hi;
    *reinterpret_cast<uint32_t*>(dst + 256) = lo;
}

// ---------------------------------------------------------------------------
__global__ __launch_bounds__(THREADS, 2)
void fe_mma_kernel(const float* __restrict__ cont,   // [N,4]
                   const float* __restrict__ freqs,  // [4,64]
                   const float* __restrict__ w1,     // [4,129,128]
                   const float* __restrict__ b1,     // [4,128]
                   const float* __restrict__ ln1g,   // [4,128]
                   const float* __restrict__ ln1b,   // [4,128]
                   const float* __restrict__ b2,     // [4,128]
                   const float* __restrict__ outg,   // [128]
                   const float* __restrict__ outb,   // [128]
                   const float* __restrict__ b3,     // [128]
                   float* __restrict__ out)          // [N,128]
{
    extern __shared__ unsigned char smem[];
    const uint32_t sbase = smem_u32(smem);
    float2* red = reinterpret_cast<float2*>(smem + REDO);  // [4 wx][64 rows]

    const int tid  = threadIdx.x;
    const int lane = tid & 31;
    const int wid  = tid >> 5;
    const int wy = wid & 1, wx = wid >> 1;
    const int rg = wy * 32, nb = wx * 32;
    const int g = lane >> 2, m = lane & 3;
    const int row0 = blockIdx.x * TM;

    int rr[4];
#pragma unroll
    for (int j = 0; j < 4; ++j) rr[j] = rg + j * 8 + g;

    const uint32_t aBase = sbase + SA
        + (uint32_t)(rg + (lane & 7) + 8 * ((lane >> 3) & 1)) * RS
        + (uint32_t)(lane >> 4) * 16u;
    const uint32_t bBase = sbase + SB
        + (uint32_t)(nb + (lane & 7) + 8 * (lane >> 4)) * RS
        + (uint32_t)((lane >> 3) & 1) * 16u;

    float accE[2][4][4];
#pragma unroll
    for (int i = 0; i < 2; ++i)
#pragma unroll
        for (int j = 0; j < 4; ++j)
#pragma unroll
            for (int q = 0; q < 4; ++q) accE[i][j][q] = 0.0f;

    const int frow = tid >> 2;          // featgen: 4 threads per row
    const int fb   = (tid & 3) * 16;    // 16 freqs each

    // hoisted: featgen row's cont values for all 4 d (one float4 LDG)
    const float4 xc4 = *reinterpret_cast<const float4*>(cont + (row0 + frow) * 4);

#pragma unroll 1
    for (int d = 0; d < 4; ++d) {
        __syncthreads();  // s_A/s_B reuse guard

        // stage w1[d] image
        {
            const unsigned char* src = g_wimg + d * IMG;
            for (int i = tid; i < IMG / 16; i += THREADS)
                cp_async16(sbase + SB + (uint32_t)i * 16u, src + i * 16);
            CP_COMMIT();
        }
        // featgen -> s_A (cos at k[0,64), sin at k[64,128), lo at +256 B)
        {
            const float x = (d == 0) ? xc4.x : (d == 1) ? xc4.y
                          : (d == 2) ? xc4.z : xc4.w;
            uint32_t chi[8], clo[8], shi[8], slo[8];
#pragma unroll
            for (int p = 0; p < 8; ++p) {
                const float f0 = freqs[d * 64 + fb + 2 * p];
                const float f1 = freqs[d * 64 + fb + 2 * p + 1];
                float c0, s0, c1, s1;
                __sincosf(x * f0 * 6.283185307179586477f, &s0, &c0);
                __sincosf(x * f1 * 6.283185307179586477f, &s1, &c1);
                pack_hilo(c0, c1, chi[p], clo[p]);
                pack_hilo(s0, s1, shi[p], slo[p]);
            }
            unsigned char* rowp = smem + SA + frow * RS;
            *reinterpret_cast<uint4*>(rowp + fb * 2)            = make_uint4(chi[0], chi[1], chi[2], chi[3]);
            *reinterpret_cast<uint4*>(rowp + fb * 2 + 16)       = make_uint4(chi[4], chi[5], chi[6], chi[7]);
            *reinterpret_cast<uint4*>(rowp + 128 + fb * 2)      = make_uint4(shi[0], shi[1], shi[2], shi[3]);
            *reinterpret_cast<uint4*>(rowp + 128 + fb * 2 + 16) = make_uint4(shi[4], shi[5], shi[6], shi[7]);
            *reinterpret_cast<uint4*>(rowp + 256 + fb * 2)      = make_uint4(clo[0], clo[1], clo[2], clo[3]);
            *reinterpret_cast<uint4*>(rowp + 256 + fb * 2 + 16) = make_uint4(clo[4], clo[5], clo[6], clo[7]);
            *reinterpret_cast<uint4*>(rowp + 384 + fb * 2)      = make_uint4(slo[0], slo[1], slo[2], slo[3]);
            *reinterpret_cast<uint4*>(rowp + 384 + fb * 2 + 16) = make_uint4(slo[4], slo[5], slo[6], slo[7]);
        }
        CP_WAIT0();
        __syncthreads();

        // ---- GEMM1 ----
        float acc[2][4][4];
#pragma unroll
        for (int i = 0; i < 2; ++i)
#pragma unroll
            for (int j = 0; j < 4; ++j)
#pragma unroll
                for (int q = 0; q < 4; ++q) acc[i][j][q] = 0.0f;
        gemm_bf16x3(aBase, bBase, acc);
        __syncthreads();  // all reads of s_A/s_B done

        // stage w2[d] image (overlaps epilogue)
        {
            const unsigned char* src = g_wimg + (4 + d) * IMG;
            for (int i = tid; i < IMG / 16; i += THREADS)
                cp_async16(sbase + SB + (uint32_t)i * 16u, src + i * 16);
            CP_COMMIT();
        }
        // ---- epi1: + x*w1_last + b1, LN, ReLU -> s_A (bf16 hi/lo) ----
        {
            const float* w1l = w1 + d * (129 * 128) + 128 * 128;
            const float* b1d = b1 + d * 128;
            const float* gd  = ln1g + d * 128;
            const float* bd  = ln1b + d * 128;
            // hoisted loads (before any barrier asm pins them)
            float2 wl[4], bb[4], gg[4], ee[4];
#pragma unroll
            for (int nt = 0; nt < 4; ++nt) {
                const int c = nb + 8 * nt + 2 * m;
                wl[nt] = *reinterpret_cast<const float2*>(w1l + c);
                bb[nt] = *reinterpret_cast<const float2*>(b1d + c);
                gg[nt] = *reinterpret_cast<const float2*>(gd + c);
                ee[nt] = *reinterpret_cast<const float2*>(bd + c);
            }
            float v[4][4][2];
            float sum[4], sq[4];
#pragma unroll
            for (int j = 0; j < 4; ++j) {
                const float xr = cont[(row0 + rr[j]) * 4 + d];
                float s = 0.f, q = 0.f;
#pragma unroll
                for (int nt = 0; nt < 4; ++nt) {
                    const float v0 = acc[j >> 1][nt][2 * (j & 1)]     + xr * wl[nt].x + bb[nt].x;
                    const float v1 = acc[j >> 1][nt][2 * (j & 1) + 1] + xr * wl[nt].y + bb[nt].y;
                    v[j][nt][0] = v0; v[j][nt][1] = v1;
                    s += v0 + v1; q += v0 * v0 + v1 * v1;
                }
                sum[j] = s; sq[j] = q;
            }
#pragma unroll
            for (int msk = 1; msk <= 2; msk <<= 1)
#pragma unroll
                for (int j = 0; j < 4; ++j) {
                    sum[j] += __shfl_xor_sync(0xffffffffu, sum[j], msk);
                    sq[j]  += __shfl_xor_sync(0xffffffffu, sq[j],  msk);
                }
            if (m == 0)
#pragma unroll
                for (int j = 0; j < 4; ++j)
                    red[wx * 64 + rr[j]] = make_float2(sum[j], sq[j]);
            BAR_GRP(wy + 1);
#pragma unroll
            for (int j = 0; j < 4; ++j) {
#pragma unroll
                for (int ox = 0; ox < 4; ++ox)
                    if (ox != wx) {
                        const float2 o = red[ox * 64 + rr[j]];
                        sum[j] += o.x; sq[j] += o.y;
                    }
            }
#pragma unroll
            for (int j = 0; j < 4; ++j) {
                const float mu = sum[j] * (1.0f / 128.0f);
                const float rs = rsqrtf(sq[j] * (1.0f / 128.0f) - mu * mu + 1e-5f);
                unsigned char* rowp = smem + SA + rr[j] * RS;
#pragma unroll
                for (int nt = 0; nt < 4; ++nt) {
                    const int c = nb + 8 * nt + 2 * m;
                    const float h0 = fmaxf((v[j][nt][0] - mu) * rs * gg[nt].x + ee[nt].x, 0.f);
                    const float h1 = fmaxf((v[j][nt][1] - mu) * rs * gg[nt].y + ee[nt].y, 0.f);
                    uint32_t hi, lo;
                    pack_hilo(h0, h1, hi, lo);
                    *reinterpret_cast<uint32_t*>(rowp + c * 2)       = hi;
                    *reinterpret_cast<uint32_t*>(rowp + 256 + c * 2) = lo;
                }
            }
        }
        CP_WAIT0();
        __syncthreads();

        // ---- GEMM2 -> accE (accumulated over d) ----
        gemm_bf16x3(aBase, bBase, accE);
    }

    __syncthreads();
    // stage w3 image
    {
        const unsigned char* src = g_wimg + 8 * IMG;
        for (int i = tid; i < IMG / 16; i += THREADS)
            cp_async16(sbase + SB + (uint32_t)i * 16u, src + i * 16);
        CP_COMMIT();
    }
    // ---- epi2: + sum_d b2, LN(outg,outb), ReLU -> s_A ----
    {
        float v[4][4][2];
        float sum[4], sq[4];
        float2 bs[4], gg[4], ee[4];
#pragma unroll
        for (int nt = 0; nt < 4; ++nt) {
            const int c = nb + 8 * nt + 2 * m;
            bs[nt].x = b2[c] + b2[128 + c] + b2[256 + c] + b2[384 + c];
            bs[nt].y = b2[c + 1] + b2[128 + c + 1] + b2[256 + c + 1] + b2[384 + c + 1];
            gg[nt] = *reinterpret_cast<const float2*>(outg + c);
            ee[nt] = *reinterpret_cast<const float2*>(outb + c);
        }
#pragma unroll
        for (int j = 0; j < 4; ++j) {
            float s = 0.f, q = 0.f;
#pragma unroll
            for (int nt = 0; nt < 4; ++nt) {
                const float v0 = accE[j >> 1][nt][2 * (j & 1)]     + bs[nt].x;
                const float v1 = accE[j >> 1][nt][2 * (j & 1) + 1] + bs[nt].y;
                v[j][nt][0] = v0; v[j][nt][1] = v1;
                s += v0 + v1; q += v0 * v0 + v1 * v1;
            }
            sum[j] = s; sq[j] = q;
        }
#pragma unroll
        for (int msk = 1; msk <= 2; msk <<= 1)
#pragma unroll
            for (int j = 0; j < 4; ++j) {
                sum[j] += __shfl_xor_sync(0xffffffffu, sum[j], msk);
                sq[j]  += __shfl_xor_sync(0xffffffffu, sq[j],  msk);
            }
        if (m == 0)
#pragma unroll
            for (int j = 0; j < 4; ++j)
                red[wx * 64 + rr[j]] = make_float2(sum[j], sq[j]);
        BAR_GRP(wy + 1);
#pragma unroll
        for (int j = 0; j < 4; ++j) {
#pragma unroll
            for (int ox = 0; ox < 4; ++ox)
                if (ox != wx) {
                    const float2 o = red[ox * 64 + rr[j]];
                    sum[j] += o.x; sq[j] += o.y;
                }
        }
#pragma unroll
        for (int j = 0; j < 4; ++j) {
            const float mu = sum[j] * (1.0f / 128.0f);
            const float rs = rsqrtf(sq[j] * (1.0f / 128.0f) - mu * mu + 1e-5f);
            unsigned char* rowp = smem + SA + rr[j] * RS;
#pragma unroll
            for (int nt = 0; nt < 4; ++nt) {
                const int c = nb + 8 * nt + 2 * m;
                const float h0 = fmaxf((v[j][nt][0] - mu) * rs * gg[nt].x + ee[nt].x, 0.f);
                const float h1 = fmaxf((v[j][nt][1] - mu) * rs * gg[nt].y + ee[nt].y, 0.f);
                uint32_t hi, lo;
                pack_hilo(h0, h1, hi, lo);
                *reinterpret_cast<uint32_t*>(rowp + c * 2)       = hi;
                *reinterpret_cast<uint32_t*>(rowp + 256 + c * 2) = lo;
            }
        }
    }
    CP_WAIT0();
    __syncthreads();

    // ---- GEMM3 + b3 -> out (b3 hoisted before GEMM so latency hides) ----
    float2 bb3[4];
#pragma unroll
    for (int nt = 0; nt < 4; ++nt)
        bb3[nt] = *reinterpret_cast<const float2*>(b3 + nb + 8 * nt + 2 * m);

    float acc3[2][4][4];
#pragma unroll
    for (int i = 0; i < 2; ++i)
#pragma unroll
        for (int j = 0; j < 4; ++j)
#pragma unroll
            for (int q = 0; q < 4; ++q) acc3[i][j][q] = 0.0f;
    gemm_bf16x3(aBase, bBase, acc3);

#pragma unroll
    for (int j = 0; j < 4; ++j) {
        float* orow = out + (size_t)(row0 + rr[j]) * 128;
#pragma unroll
        for (int nt = 0; nt < 4; ++nt) {
            const int c = nb + 8 * nt + 2 * m;
            *reinterpret_cast<float2*>(orow + c) =
                make_float2(acc3[j >> 1][nt][2 * (j & 1)]     + bb3[nt].x,
                            acc3[j >> 1][nt][2 * (j & 1) + 1] + bb3[nt].y);
        }
    }
}

// ---------------------------------------------------------------------------
extern "C" void kernel_launch(void* const* d_in, const int* in_sizes, int n_in,
                              void* d_out, int out_size)
{
    const float* cont  = (const float*)d_in[0];
    const float* freqs = (const float*)d_in[1];
    const float* w1    = (const float*)d_in[2];
    const float* b1    = (const float*)d_in[3];
    const float* ln1g  = (const float*)d_in[4];
    const float* ln1b  = (const float*)d_in[5];
    const float* w2    = (const float*)d_in[6];
    const float* b2    = (const float*)d_in[7];
    const float* outg  = (const float*)d_in[8];
    const float* outb  = (const float*)d_in[9];
    const float* w3    = (const float*)d_in[10];
    const float* b3    = (const float*)d_in[11];
    float* out = (float*)d_out;

    convert_weights_kernel<<<288, 256>>>(w1, w2, w3);

    cudaFuncSetAttribute(fe_mma_kernel,
                         cudaFuncAttributeMaxDynamicSharedMemorySize, SMEM_BYTES);
    fe_mma_kernel<<<NROWS / TM, THREADS, SMEM_BYTES>>>(
        cont, freqs, w1, b1, ln1g, ln1b, b2, outg, outb, b3, out);
}

// round 17
// speedup vs baseline: 1.0950x; 1.0198x over previous
#include <cuda_runtime.h>
#include <stdint.h>

// ============================================================================
// FourierEmbedding via warp-level bf16 mma.sync (m16n8k16), 3-term hi/lo split.
// R16 = R13 + per-slice EARLY staging: each wx-pair (2 warps sharing a 32-row
// B slice) syncs on a 64-thread named barrier right after a GEMM and streams
// the NEXT image's own slice immediately -> every cp.async gets a full-GEMM
// window instead of an epilogue window; one full __syncthreads per d removed.
// Sync structure per d: S1(top) -> featgen -> WAIT+S2 -> GEMM1 -> pairbar ->
// stage w2 slice -> epi (row-group bar) -> WAIT+S3 -> GEMM2 -> pairbar ->
// stage w1[d+1]/w3 slice.
// CTA = 64 rows, 256 threads, warp grid 2(row)x4(col), warp tile 32x32,
// fully unrolled ks loop. Weight images: [n][k] row-major, hi bf16 at k*2,
// lo at 256+k*2, row stride 528 B (conflict-free ldmatrix).
// Barrier ids: 1,2 = row-group (128 thr); 3..6 = wx pairs (64 thr).
// ============================================================================

static constexpr int NROWS   = 131072;
static constexpr int TM      = 64;
static constexpr int THREADS = 256;
static constexpr int RS      = 528;               // image row stride (bytes)
static constexpr int IMG     = 128 * RS;          // 67584 B per weight image
static constexpr int SLICE   = 32 * RS;           // 16896 B per wx slice
static constexpr int SA      = 0;                 // A image: 64 rows
static constexpr int SB      = TM * RS;           // 33792
static constexpr int REDO    = SB + IMG;          // 101376
static constexpr int SMEM_BYTES = REDO + 4 * 64 * 8;  // 103424 -> 2 CTA/SM

__device__ __align__(16) unsigned char g_wimg[9 * IMG];

// ---------------------------------------------------------------------------
static __device__ __forceinline__ uint32_t smem_u32(const void* p) {
    uint32_t a;
    asm("{ .reg .u64 t; cvta.to.shared.u64 t, %1; cvt.u32.u64 %0, t; }"
        : "=r"(a) : "l"(p));
    return a;
}
static __device__ __forceinline__ uint32_t cvt_bf16x2(float b, float a) {
    uint32_t r;
    asm("cvt.rn.bf16x2.f32 %0, %1, %2;" : "=r"(r) : "f"(b), "f"(a));
    return r;
}
static __device__ __forceinline__ void pack_hilo(float a, float b,
                                                 uint32_t& hi, uint32_t& lo) {
    hi = cvt_bf16x2(b, a);
    const float ra = a - __uint_as_float(hi << 16);
    const float rb = b - __uint_as_float(hi & 0xffff0000u);
    lo = cvt_bf16x2(rb, ra);
}
static __device__ __forceinline__ void cp_async16(uint32_t dst, const void* src) {
    asm volatile("cp.async.cg.shared.global [%0], [%1], 16;"
                 :: "r"(dst), "l"(src) : "memory");
}
#define CP_COMMIT() asm volatile("cp.async.commit_group;" ::: "memory")
#define CP_WAIT0()  asm volatile("cp.async.wait_group 0;" ::: "memory")
#define BAR_GRP(id)  asm volatile("bar.sync %0, 128;" :: "r"(id) : "memory")
#define BAR_PAIR(id) asm volatile("bar.sync %0, 64;"  :: "r"(id) : "memory")

static __device__ __forceinline__ void ldsm4(uint32_t (&r)[4], uint32_t addr) {
    asm volatile("ldmatrix.sync.aligned.m8n8.x4.shared.b16 {%0,%1,%2,%3}, [%4];"
        : "=r"(r[0]), "=r"(r[1]), "=r"(r[2]), "=r"(r[3]) : "r"(addr));
}
static __device__ __forceinline__ void mma16816(float* c, const uint32_t* a,
                                                uint32_t b0, uint32_t b1) {
    asm("mma.sync.aligned.m16n8k16.row.col.f32.bf16.bf16.f32 "
        "{%0,%1,%2,%3},{%4,%5,%6,%7},{%8,%9},{%0,%1,%2,%3};"
        : "+f"(c[0]), "+f"(c[1]), "+f"(c[2]), "+f"(c[3])
        : "r"(a[0]), "r"(a[1]), "r"(a[2]), "r"(a[3]), "r"(b0), "r"(b1));
}

// K=128, 3-term bf16 GEMM. Warp tile 32x32, fully unrolled (R13).
static __device__ __forceinline__ void gemm_bf16x3(uint32_t aB, uint32_t bB,
                                                   float (&acc)[2][4][4]) {
#pragma unroll
    for (int ks = 0; ks < 8; ++ks) {
        const uint32_t kb = (uint32_t)ks * 32u;
        uint32_t ah[2][4], al[2][4], bh[2][4], bl[2][4];
        ldsm4(ah[0], aB + kb);
        ldsm4(ah[1], aB + 16u * RS + kb);
        ldsm4(bh[0], bB + kb);
        ldsm4(bh[1], bB + 16u * RS + kb);
        ldsm4(al[0], aB + kb + 256u);
        ldsm4(al[1], aB + 16u * RS + kb + 256u);
#pragma unroll
        for (int mt = 0; mt < 2; ++mt)
#pragma unroll
            for (int p = 0; p < 2; ++p) {
                mma16816(acc[mt][2 * p],     ah[mt], bh[p][0], bh[p][1]);
                mma16816(acc[mt][2 * p + 1], ah[mt], bh[p][2], bh[p][3]);
            }
        ldsm4(bl[0], bB + kb + 256u);
        ldsm4(bl[1], bB + 16u * RS + kb + 256u);
#pragma unroll
        for (int mt = 0; mt < 2; ++mt)
#pragma unroll
            for (int p = 0; p < 2; ++p) {
                mma16816(acc[mt][2 * p],     al[mt], bh[p][0], bh[p][1]);
                mma16816(acc[mt][2 * p + 1], al[mt], bh[p][2], bh[p][3]);
            }
#pragma unroll
        for (int mt = 0; mt < 2; ++mt)
#pragma unroll
            for (int p = 0; p < 2; ++p) {
                mma16816(acc[mt][2 * p],     ah[mt], bl[p][0], bl[p][1]);
                mma16816(acc[mt][2 * p + 1], ah[mt], bl[p][2], bl[p][3]);
            }
    }
}

// ---------------------------------------------------------------------------
// pre-kernel: build 9 weight images (transposed [n][k], hi/lo bf16, stride RS)
// ---------------------------------------------------------------------------
__global__ void convert_weights_kernel(const float* __restrict__ w1,
                                       const float* __restrict__ w2,
                                       const float* __restrict__ w3) {
    const int t = blockIdx.x * blockDim.x + threadIdx.x;  // 9*128*64 = 73728
    const int img = t >> 13;
    const int rem = t & 8191;
    const int n = rem >> 6;
    const int p = rem & 63;          // k-pair
    const float* src;
    if (img < 4)      src = w1 + img * (129 * 128);
    else if (img < 8) src = w2 + (img - 4) * (128 * 128);
    else              src = w3;
    const float v0 = src[(2 * p) * 128 + n];
    const float v1 = src[(2 * p + 1) * 128 + n];
    uint32_t hi, lo;
    pack_hilo(v0, v1, hi, lo);
    unsigned char* dst = g_wimg + img * IMG + n * RS + p * 4;
    *reinterpret_cast<uint32_t*>(dst)       = hi;
    *reinterpret_cast<uint32_t*>(dst + 256) = lo;
}

// ---------------------------------------------------------------------------
__global__ __launch_bounds__(THREADS, 2)
void fe_mma_kernel(const float* __restrict__ cont,   // [N,4]
                   const float* __restrict__ freqs,  // [4,64]
                   const float* __restrict__ w1,     // [4,129,128]
                   const float* __restrict__ b1,     // [4,128]
                   const float* __restrict__ ln1g,   // [4,128]
                   const float* __restrict__ ln1b,   // [4,128]
                   const float* __restrict__ b2,     // [4,128]
                   const float* __restrict__ outg,   // [128]
                   const float* __restrict__ outb,   // [128]
                   const float* __restrict__ b3,     // [128]
                   float* __restrict__ out)          // [N,128]
{
    extern __shared__ unsigned char smem[];
    const uint32_t sbase = smem_u32(smem);
    float2* red = reinterpret_cast<float2*>(smem + REDO);  // [4 wx][64 rows]

    const int tid  = threadIdx.x;
    const int lane = tid & 31;
    const int wid  = tid >> 5;
    const int wy = wid & 1, wx = wid >> 1;
    const int rg = wy * 32, nb = wx * 32;
    const int g = lane >> 2, m = lane & 3;
    const int row0 = blockIdx.x * TM;
    const int pid  = wy * 32 + lane;   // thread index within the wx pair (0..63)

    int rr[4];
#pragma unroll
    for (int j = 0; j < 4; ++j) rr[j] = rg + j * 8 + g;

    const uint32_t aBase = sbase + SA
        + (uint32_t)(rg + (lane & 7) + 8 * ((lane >> 3) & 1)) * RS
        + (uint32_t)(lane >> 4) * 16u;
    const uint32_t bBase = sbase + SB
        + (uint32_t)(nb + (lane & 7) + 8 * (lane >> 4)) * RS
        + (uint32_t)((lane >> 3) & 1) * 16u;

    // stage THIS pair's 32-row slice of image `img` (1056 x 16B chunks / pair)
    auto stage_slice = [&](int img) {
        const unsigned char* src = g_wimg + (size_t)img * IMG + (size_t)wx * SLICE;
        const uint32_t dst0 = sbase + SB + (uint32_t)wx * SLICE;
        for (int i = pid; i < SLICE / 16; i += 64)
            cp_async16(dst0 + (uint32_t)i * 16u, src + i * 16);
        CP_COMMIT();
    };

    float accE[2][4][4];
#pragma unroll
    for (int i = 0; i < 2; ++i)
#pragma unroll
        for (int j = 0; j < 4; ++j)
#pragma unroll
            for (int q = 0; q < 4; ++q) accE[i][j][q] = 0.0f;

    const int frow = tid >> 2;          // featgen: 4 threads per row
    const int fb   = (tid & 3) * 16;    // 16 freqs each

    // prologue: whole-CTA stage of w1[0]
    {
        const unsigned char* src = g_wimg;
        for (int i = tid; i < IMG / 16; i += THREADS)
            cp_async16(sbase + SB + (uint32_t)i * 16u, src + i * 16);
        CP_COMMIT();
    }

#pragma unroll 1
    for (int d = 0; d < 4; ++d) {
        __syncthreads();  // S1: prev GEMM2 s_A reads done -> featgen may write

        // featgen -> s_A (cos at k[0,64), sin at k[64,128), lo at +256 B)
        {
            const float x = cont[(row0 + frow) * 4 + d];
            uint32_t chi[8], clo[8], shi[8], slo[8];
#pragma unroll
            for (int p = 0; p < 8; ++p) {
                const float f0 = freqs[d * 64 + fb + 2 * p];
                const float f1 = freqs[d * 64 + fb + 2 * p + 1];
                float c0, s0, c1, s1;
                __sincosf(x * f0 * 6.283185307179586477f, &s0, &c0);
                __sincosf(x * f1 * 6.283185307179586477f, &s1, &c1);
                pack_hilo(c0, c1, chi[p], clo[p]);
                pack_hilo(s0, s1, shi[p], slo[p]);
            }
            unsigned char* rowp = smem + SA + frow * RS;
            *reinterpret_cast<uint4*>(rowp + fb * 2)            = make_uint4(chi[0], chi[1], chi[2], chi[3]);
            *reinterpret_cast<uint4*>(rowp + fb * 2 + 16)       = make_uint4(chi[4], chi[5], chi[6], chi[7]);
            *reinterpret_cast<uint4*>(rowp + 128 + fb * 2)      = make_uint4(shi[0], shi[1], shi[2], shi[3]);
            *reinterpret_cast<uint4*>(rowp + 128 + fb * 2 + 16) = make_uint4(shi[4], shi[5], shi[6], shi[7]);
            *reinterpret_cast<uint4*>(rowp + 256 + fb * 2)      = make_uint4(clo[0], clo[1], clo[2], clo[3]);
            *reinterpret_cast<uint4*>(rowp + 256 + fb * 2 + 16) = make_uint4(clo[4], clo[5], clo[6], clo[7]);
            *reinterpret_cast<uint4*>(rowp + 384 + fb * 2)      = make_uint4(slo[0], slo[1], slo[2], slo[3]);
            *reinterpret_cast<uint4*>(rowp + 384 + fb * 2 + 16) = make_uint4(slo[4], slo[5], slo[6], slo[7]);
        }
        CP_WAIT0();        // my w1[d] slice (or prologue) copies done
        __syncthreads();   // S2: all slices + featgen visible

        // ---- GEMM1 ----
        float acc[2][4][4];
#pragma unroll
        for (int i = 0; i < 2; ++i)
#pragma unroll
            for (int j = 0; j < 4; ++j)
#pragma unroll
                for (int q = 0; q < 4; ++q) acc[i][j][q] = 0.0f;
        gemm_bf16x3(aBase, bBase, acc);

        // pair done reading slice wx -> stream w2[d] slice NOW
        BAR_PAIR(3 + wx);
        stage_slice(4 + d);

        // ---- epi1: + x*w1_last + b1, LN, ReLU -> s_A (bf16 hi/lo) ----
        {
            const float* w1l = w1 + d * (129 * 128) + 128 * 128;
            const float* b1d = b1 + d * 128;
            float2 wl[4], bb[4];
#pragma unroll
            for (int nt = 0; nt < 4; ++nt) {
                const int c = nb + 8 * nt + 2 * m;
                wl[nt] = *reinterpret_cast<const float2*>(w1l + c);
                bb[nt] = *reinterpret_cast<const float2*>(b1d + c);
            }
            float v[4][4][2];
            float sum[4], sq[4];
#pragma unroll
            for (int j = 0; j < 4; ++j) {
                const float xr = cont[(row0 + rr[j]) * 4 + d];
                float s = 0.f, q = 0.f;
#pragma unroll
                for (int nt = 0; nt < 4; ++nt) {
                    const float v0 = acc[j >> 1][nt][2 * (j & 1)]     + xr * wl[nt].x + bb[nt].x;
                    const float v1 = acc[j >> 1][nt][2 * (j & 1) + 1] + xr * wl[nt].y + bb[nt].y;
                    v[j][nt][0] = v0; v[j][nt][1] = v1;
                    s += v0 + v1; q += v0 * v0 + v1 * v1;
                }
                sum[j] = s; sq[j] = q;
            }
#pragma unroll
            for (int msk = 1; msk <= 2; msk <<= 1)
#pragma unroll
                for (int j = 0; j < 4; ++j) {
                    sum[j] += __shfl_xor_sync(0xffffffffu, sum[j], msk);
                    sq[j]  += __shfl_xor_sync(0xffffffffu, sq[j],  msk);
                }
            if (m == 0)
#pragma unroll
                for (int j = 0; j < 4; ++j)
                    red[wx * 64 + rr[j]] = make_float2(sum[j], sq[j]);
            BAR_GRP(wy + 1);   // row-group: also orders h-writes vs GEMM1 reads
#pragma unroll
            for (int j = 0; j < 4; ++j) {
#pragma unroll
                for (int ox = 0; ox < 4; ++ox)
                    if (ox != wx) {
                        const float2 o = red[ox * 64 + rr[j]];
                        sum[j] += o.x; sq[j] += o.y;
                    }
            }
            const float* gd = ln1g + d * 128;
            const float* bd = ln1b + d * 128;
#pragma unroll
            for (int j = 0; j < 4; ++j) {
                const float mu = sum[j] * (1.0f / 128.0f);
                const float rs = rsqrtf(sq[j] * (1.0f / 128.0f) - mu * mu + 1e-5f);
                unsigned char* rowp = smem + SA + rr[j] * RS;
#pragma unroll
                for (int nt = 0; nt < 4; ++nt) {
                    const int c = nb + 8 * nt + 2 * m;
                    const float2 gg = *reinterpret_cast<const float2*>(gd + c);
                    const float2 ee = *reinterpret_cast<const float2*>(bd + c);
                    const float h0 = fmaxf((v[j][nt][0] - mu) * rs * gg.x + ee.x, 0.f);
                    const float h1 = fmaxf((v[j][nt][1] - mu) * rs * gg.y + ee.y, 0.f);
                    uint32_t hi, lo;
                    pack_hilo(h0, h1, hi, lo);
                    *reinterpret_cast<uint32_t*>(rowp + c * 2)       = hi;
                    *reinterpret_cast<uint32_t*>(rowp + 256 + c * 2) = lo;
                }
            }
        }
        CP_WAIT0();        // my w2[d] slice done
        __syncthreads();   // S3: all w2 slices + h visible

        // ---- GEMM2 -> accE (accumulated over d) ----
        gemm_bf16x3(aBase, bBase, accE);

        // pair done reading slice wx -> stream next image's slice NOW
        BAR_PAIR(3 + wx);
        stage_slice(d < 3 ? d + 1 : 8);   // w1[d+1] or w3
    }

    // ---- epi2: + sum_d b2, LN(outg,outb), ReLU -> s_A ----
    {
        float v[4][4][2];
        float sum[4], sq[4];
        float2 bs[4];
#pragma unroll
        for (int nt = 0; nt < 4; ++nt) {
            const int c = nb + 8 * nt + 2 * m;
            bs[nt].x = b2[c] + b2[128 + c] + b2[256 + c] + b2[384 + c];
            bs[nt].y = b2[c + 1] + b2[128 + c + 1] + b2[256 + c + 1] + b2[384 + c + 1];
        }
#pragma unroll
        for (int j = 0; j < 4; ++j) {
            float s = 0.f, q = 0.f;
#pragma unroll
            for (int nt = 0; nt < 4; ++nt) {
                const float v0 = accE[j >> 1][nt][2 * (j & 1)]     + bs[nt].x;
                const float v1 = accE[j >> 1][nt][2 * (j & 1) + 1] + bs[nt].y;
                v[j][nt][0] = v0; v[j][nt][1] = v1;
                s += v0 + v1; q += v0 * v0 + v1 * v1;
            }
            sum[j] = s; sq[j] = q;
        }
#pragma unroll
        for (int msk = 1; msk <= 2; msk <<= 1)
#pragma unroll
            for (int j = 0; j < 4; ++j) {
                sum[j] += __shfl_xor_sync(0xffffffffu, sum[j], msk);
                sq[j]  += __shfl_xor_sync(0xffffffffu, sq[j],  msk);
            }
        if (m == 0)
#pragma unroll
            for (int j = 0; j < 4; ++j)
                red[wx * 64 + rr[j]] = make_float2(sum[j], sq[j]);
        BAR_GRP(wy + 1);   // row-group: orders h-writes vs GEMM2 reads
#pragma unroll
        for (int j = 0; j < 4; ++j) {
#pragma unroll
            for (int ox = 0; ox < 4; ++ox)
                if (ox != wx) {
                    const float2 o = red[ox * 64 + rr[j]];
                    sum[j] += o.x; sq[j] += o.y;
                }
        }
#pragma unroll
        for (int j = 0; j < 4; ++j) {
            const float mu = sum[j] * (1.0f / 128.0f);
            const float rs = rsqrtf(sq[j] * (1.0f / 128.0f) - mu * mu + 1e-5f);
            unsigned char* rowp = smem + SA + rr[j] * RS;
#pragma unroll
            for (int nt = 0; nt < 4; ++nt) {
                const int c = nb + 8 * nt + 2 * m;
                const float2 gg = *reinterpret_cast<const float2*>(outg + c);
                const float2 ee = *reinterpret_cast<const float2*>(outb + c);
                const float h0 = fmaxf((v[j][nt][0] - mu) * rs * gg.x + ee.x, 0.f);
                const float h1 = fmaxf((v[j][nt][1] - mu) * rs * gg.y + ee.y, 0.f);
                uint32_t hi, lo;
                pack_hilo(h0, h1, hi, lo);
                *reinterpret_cast<uint32_t*>(rowp + c * 2)       = hi;
                *reinterpret_cast<uint32_t*>(rowp + 256 + c * 2) = lo;
            }
        }
    }
    CP_WAIT0();            // my w3 slice done
    __syncthreads();       // all w3 slices + out-LN h visible

    // ---- GEMM3 + b3 -> out ----
    float acc3[2][4][4];
#pragma unroll
    for (int i = 0; i < 2; ++i)
#pragma unroll
        for (int j = 0; j < 4; ++j)
#pragma unroll
            for (int q = 0; q < 4; ++q) acc3[i][j][q] = 0.0f;
    gemm_bf16x3(aBase, bBase, acc3);

#pragma unroll
    for (int j = 0; j < 4; ++j) {
        float* orow = out + (size_t)(row0 + rr[j]) * 128;
#pragma unroll
        for (int nt = 0; nt < 4; ++nt) {
            const int c = nb + 8 * nt + 2 * m;
            const float2 bb = *reinterpret_cast<const float2*>(b3 + c);
            *reinterpret_cast<float2*>(orow + c) =
                make_float2(acc3[j >> 1][nt][2 * (j & 1)]     + bb.x,
                            acc3[j >> 1][nt][2 * (j & 1) + 1] + bb.y);
        }
    }
}

// ---------------------------------------------------------------------------
extern "C" void kernel_launch(void* const* d_in, const int* in_sizes, int n_in,
                              void* d_out, int out_size)
{
    const float* cont  = (const float*)d_in[0];
    const float* freqs = (const float*)d_in[1];
    const float* w1    = (const float*)d_in[2];
    const float* b1    = (const float*)d_in[3];
    const float* ln1g  = (const float*)d_in[4];
    const float* ln1b  = (const float*)d_in[5];
    const float* w2    = (const float*)d_in[6];
    const float* b2    = (const float*)d_in[7];
    const float* outg  = (const float*)d_in[8];
    const float* outb  = (const float*)d_in[9];
    const float* w3    = (const float*)d_in[10];
    const float* b3    = (const float*)d_in[11];
    float* out = (float*)d_out;

    convert_weights_kernel<<<288, 256>>>(w1, w2, w3);

    cudaFuncSetAttribute(fe_mma_kernel,
                         cudaFuncAttributeMaxDynamicSharedMemorySize, SMEM_BYTES);
    fe_mma_kernel<<<NROWS / TM, THREADS, SMEM_BYTES>>>(
        cont, freqs, w1, b1, ln1g, ln1b, b2, outg, outb, b3, out);
}